// round 11
// baseline (speedup 1.0000x reference)
#include <cuda_runtime.h>

#define NN_MAX 100000
#define EE_MAX 1600000
#define D 64
#define EPSV 1e-12f
#define SCAN_B 1024

// Scratch (no allocations allowed)
__device__ float g_invn[NN_MAX];        // 1/max(||feat_row||, eps)
__device__ int   g_hist[NN_MAX];        // in-degree (zero-on-entry invariant)
__device__ int   g_rank[EE_MAX];        // edge rank within its dst bucket
__device__ int   g_rowptr[NN_MAX + 1];  // CSR row pointers (by dst)
__device__ int   g_bsums[128];          // scan block totals
__device__ int   g_ready[128];          // scan publish flags (A zeroes)
__device__ int   g_esrc[EE_MAX];        // src ids grouped by dst

// ---------------------------------------------------------------------------
// A: per-row inverse L2 norm (warp per row) + hist/rank (edge grid-stride)
//    + zero the scan flags for kernel B.
__global__ void k_norm_hist(const float* __restrict__ feat,
                            const int* __restrict__ dst,
                            int n_nodes, int n_edges) {
    int t    = blockIdx.x * blockDim.x + threadIdx.x;
    int w    = t >> 5;
    int lane = threadIdx.x & 31;

    if (t < 128) g_ready[t] = 0;

    if (w < n_nodes) {
        float2 v = reinterpret_cast<const float2*>(feat + (size_t)w * D)[lane];
        float s = v.x * v.x + v.y * v.y;
        #pragma unroll
        for (int o = 16; o; o >>= 1) s += __shfl_xor_sync(0xffffffffu, s, o);
        if (lane == 0) g_invn[w] = 1.0f / fmaxf(sqrtf(s), EPSV);
    }

    int stride = gridDim.x * blockDim.x;
    for (int i = t; i < n_edges; i += stride)
        g_rank[i] = atomicAdd(&g_hist[dst[i]], 1);   // rank within bucket
}

// warp-shuffle inclusive scan helper
__device__ __forceinline__ int warp_iscan(int x, int lane) {
    #pragma unroll
    for (int o = 1; o < 32; o <<= 1) {
        int t = __shfl_up_sync(0xffffffffu, x, o);
        if (lane >= o) x += t;
    }
    return x;
}

// B: single-launch scan. Each of <=128 blocks scans its chunk, publishes its
// total (fenced flag), polls peers below it, adds offset -> global exclusive
// rowptr. All blocks fit in wave 1 (<=128 < 148 SMs) so polling is safe.
// Re-zeroes g_hist to restore the zero-on-entry invariant.
__global__ void k_scan(int n_nodes, int n_edges) {
    __shared__ int wsum[32];
    __shared__ int s_off;
    int i    = blockIdx.x * SCAN_B + threadIdx.x;
    int lane = threadIdx.x & 31;
    int wid  = threadIdx.x >> 5;

    int v = (i < n_nodes) ? g_hist[i] : 0;
    if (i < n_nodes) g_hist[i] = 0;                  // restore invariant
    int x = warp_iscan(v, lane);
    if (lane == 31) wsum[wid] = x;
    __syncthreads();
    if (wid == 0) wsum[lane] = warp_iscan(wsum[lane], lane);
    __syncthreads();
    int off_local = wid ? wsum[wid - 1] : 0;
    int block_total = wsum[31];

    // publish this block's total
    if (threadIdx.x == 0) {
        g_bsums[blockIdx.x] = block_total;
        __threadfence();
        atomicExch(&g_ready[blockIdx.x], 1);
    }

    // gather totals of blocks below us
    int bv = 0;
    if ((int)threadIdx.x < (int)blockIdx.x) {
        while (atomicAdd(&g_ready[threadIdx.x], 0) == 0) {}
        __threadfence();
        bv = g_bsums[threadIdx.x];
    }
    #pragma unroll
    for (int o = 16; o; o >>= 1) bv += __shfl_xor_sync(0xffffffffu, bv, o);
    __syncthreads();                 // wsum reuse barrier
    if (lane == 0) wsum[wid] = bv;
    __syncthreads();
    if (wid == 0) {
        int r = wsum[lane];
        #pragma unroll
        for (int o = 16; o; o >>= 1) r += __shfl_xor_sync(0xffffffffu, r, o);
        if (lane == 0) s_off = r;
    }
    __syncthreads();

    if (i < n_nodes) g_rowptr[i] = off_local + x - v + s_off;
    if (i == 0) g_rowptr[n_nodes] = n_edges;
}

// C: atomic-free scatter: pos = rowptr[dst] + rank (4 edges/thread)
__global__ void k_scatter(const int* __restrict__ src,
                          const int* __restrict__ dst, int n_edges) {
    int base = blockIdx.x * (blockDim.x * 4) + threadIdx.x;
    int d[4], s[4], r[4];
    bool v[4];
    #pragma unroll
    for (int k = 0; k < 4; k++) {
        int i = base + k * blockDim.x;
        v[k] = (i < n_edges);
        d[k] = v[k] ? dst[i] : 0;
        s[k] = v[k] ? src[i] : 0;
        r[k] = v[k] ? g_rank[i] : 0;
    }
    int p[4];
    #pragma unroll
    for (int k = 0; k < 4; k++)
        p[k] = g_rowptr[d[k]] + r[k];
    #pragma unroll
    for (int k = 0; k < 4; k++)
        if (v[k]) g_esrc[p[k]] = s[k];
}

// ---------------------------------------------------------------------------
// D: fused softmax + aggregation. Warp per dst, 8 lanes per edge (4 edges
// per warp-iter). __launch_bounds__(256, 6) caps regs (~42) to lift
// occupancy from 42% -> 75% ceiling; no unroll (measured neutral, costs regs).
__global__ void __launch_bounds__(256, 6)
k_agg(const float* __restrict__ feat,
      const float* __restrict__ beta,
      float* __restrict__ out, int n_nodes) {
    int w    = (blockIdx.x * blockDim.x + threadIdx.x) >> 5;
    int lane = threadIdx.x & 31;
    if (w >= n_nodes) return;
    int grp = lane >> 3;       // which edge of the quad (0..3)
    int g   = lane & 7;        // lane within group

    const float4* feat4 = reinterpret_cast<const float4*>(feat);
    float4 fda = feat4[(size_t)w * 16 + g];
    float4 fdb = feat4[(size_t)w * 16 + g + 8];
    float bscale = beta[0] * g_invn[w];     // TEMP == 1
    int beg = g_rowptr[w], end = g_rowptr[w + 1];
    int deg = end - beg;
    int nfull = deg >> 2;                   // full quads, no predication
    int rem   = deg & 3;

    float denom = 0.0f;
    float4 A = make_float4(0.f, 0.f, 0.f, 0.f);
    float4 B = make_float4(0.f, 0.f, 0.f, 0.f);

    for (int it = 0; it < nfull; it++) {
        int e = beg + it * 4 + grp;
        int s = g_esrc[e];
        float iv = g_invn[s];
        const float4* rp = feat4 + (size_t)s * 16;
        float4 a = rp[g];
        float4 b = rp[g + 8];
        float p = a.x * fda.x + a.y * fda.y + a.z * fda.z + a.w * fda.w
                + b.x * fdb.x + b.y * fdb.y + b.z * fdb.z + b.w * fdb.w;
        p += __shfl_xor_sync(0xffffffffu, p, 4);
        p += __shfl_xor_sync(0xffffffffu, p, 2);
        p += __shfl_xor_sync(0xffffffffu, p, 1);
        float ex = __expf(bscale * iv * p);
        denom += ex;
        A.x += ex * a.x; A.y += ex * a.y; A.z += ex * a.z; A.w += ex * a.w;
        B.x += ex * b.x; B.y += ex * b.y; B.z += ex * b.z; B.w += ex * b.w;
    }
    if (rem) {                              // tail quad, predicated once
        int e = beg + nfull * 4 + grp;
        bool valid = (grp < rem);
        int s = valid ? g_esrc[e] : 0;
        float iv = g_invn[s];
        const float4* rp = feat4 + (size_t)s * 16;
        float4 a = rp[g];
        float4 b = rp[g + 8];
        float p = a.x * fda.x + a.y * fda.y + a.z * fda.z + a.w * fda.w
                + b.x * fdb.x + b.y * fdb.y + b.z * fdb.z + b.w * fdb.w;
        p += __shfl_xor_sync(0xffffffffu, p, 4);
        p += __shfl_xor_sync(0xffffffffu, p, 2);
        p += __shfl_xor_sync(0xffffffffu, p, 1);
        float ex = valid ? __expf(bscale * iv * p) : 0.0f;
        denom += ex;
        A.x += ex * a.x; A.y += ex * a.y; A.z += ex * a.z; A.w += ex * a.w;
        B.x += ex * b.x; B.y += ex * b.y; B.z += ex * b.z; B.w += ex * b.w;
    }

    // combine the 4 edge-groups (lane g in each group owns the same dims)
    #pragma unroll
    for (int o = 8; o <= 16; o <<= 1) {
        denom += __shfl_xor_sync(0xffffffffu, denom, o);
        A.x += __shfl_xor_sync(0xffffffffu, A.x, o);
        A.y += __shfl_xor_sync(0xffffffffu, A.y, o);
        A.z += __shfl_xor_sync(0xffffffffu, A.z, o);
        A.w += __shfl_xor_sync(0xffffffffu, A.w, o);
        B.x += __shfl_xor_sync(0xffffffffu, B.x, o);
        B.y += __shfl_xor_sync(0xffffffffu, B.y, o);
        B.z += __shfl_xor_sync(0xffffffffu, B.z, o);
        B.w += __shfl_xor_sync(0xffffffffu, B.w, o);
    }

    if (lane < 8) {
        float r = 1.0f / fmaxf(denom, EPSV);
        float4 o1 = make_float4(A.x * r, A.y * r, A.z * r, A.w * r);
        float4 o2 = make_float4(B.x * r, B.y * r, B.z * r, B.w * r);
        float4* out4 = reinterpret_cast<float4*>(out);
        out4[(size_t)w * 16 + g]     = o1;
        out4[(size_t)w * 16 + g + 8] = o2;
    }
}

// ---------------------------------------------------------------------------
extern "C" void kernel_launch(void* const* d_in, const int* in_sizes, int n_in,
                              void* d_out, int out_size) {
    const float* feat = (const float*)d_in[0];
    const float* beta = (const float*)d_in[1];
    const int*   src  = (const int*)d_in[2];   // JAX default int32 (no x64)
    const int*   dst  = (const int*)d_in[3];
    float*       out  = (float*)d_out;

    int n_nodes = in_sizes[0] / D;
    int n_edges = in_sizes[2];
    if (n_nodes > NN_MAX) n_nodes = NN_MAX;
    if (n_edges > EE_MAX) n_edges = EE_MAX;

    const int T = 256;
    int roww_blocks = (n_nodes + 7) / 8;          // warp-per-row/dst
    int scat_blocks = (n_edges + T * 4 - 1) / (T * 4);
    int scan_blocks = (n_nodes + SCAN_B - 1) / SCAN_B;   // <= 128 required

    k_norm_hist<<<roww_blocks, T>>>(feat, dst, n_nodes, n_edges);
    k_scan     <<<scan_blocks, SCAN_B>>>(n_nodes, n_edges);
    k_scatter  <<<scat_blocks, T>>>(src, dst, n_edges);
    k_agg      <<<roww_blocks, T>>>(feat, beta, out, n_nodes);
}

// round 12
// speedup vs baseline: 1.0102x; 1.0102x over previous
#include <cuda_runtime.h>

#define NN_MAX 100000
#define EE_MAX 1600000
#define D 64
#define EPSV 1e-12f
#define SCAN_B 1024

// Scratch (no allocations allowed)
__device__ float g_invn[NN_MAX];        // 1/max(||feat_row||, eps)
__device__ int   g_hist[NN_MAX];        // in-degree (zero-on-entry invariant)
__device__ int   g_rank[EE_MAX];        // edge rank within its dst bucket
__device__ int   g_rowptr[NN_MAX + 1];  // CSR row pointers (by dst)
__device__ int   g_bsums[128];          // scan block totals
__device__ int   g_ready[128];          // scan publish flags  (zeroed by A)
__device__ int   g_ready2[128];         // rowptr-done flags    (zeroed by A)
__device__ int   g_esrc[EE_MAX];        // src ids grouped by dst

// ---------------------------------------------------------------------------
// A: per-row inverse L2 norm (warp per row) + hist/rank (edge grid-stride)
//    + zero both flag arrays for kernel B.
__global__ void k_norm_hist(const float* __restrict__ feat,
                            const int* __restrict__ dst,
                            int n_nodes, int n_edges) {
    int t    = blockIdx.x * blockDim.x + threadIdx.x;
    int w    = t >> 5;
    int lane = threadIdx.x & 31;

    if (t < 128) { g_ready[t] = 0; g_ready2[t] = 0; }

    if (w < n_nodes) {
        float2 v = reinterpret_cast<const float2*>(feat + (size_t)w * D)[lane];
        float s = v.x * v.x + v.y * v.y;
        #pragma unroll
        for (int o = 16; o; o >>= 1) s += __shfl_xor_sync(0xffffffffu, s, o);
        if (lane == 0) g_invn[w] = 1.0f / fmaxf(sqrtf(s), EPSV);
    }

    int stride = gridDim.x * blockDim.x;
    for (int i = t; i < n_edges; i += stride)
        g_rank[i] = atomicAdd(&g_hist[dst[i]], 1);   // rank within bucket
}

// warp-shuffle inclusive scan helper
__device__ __forceinline__ int warp_iscan(int x, int lane) {
    #pragma unroll
    for (int o = 1; o < 32; o <<= 1) {
        int t = __shfl_up_sync(0xffffffffu, x, o);
        if (lane >= o) x += t;
    }
    return x;
}

// B (fused scan + scatter): <=128 resident blocks.
// Phase 1: block-local scan, publish totals, poll peers -> global rowptr.
// Phase 2: publish rowptr-done, poll all -> scatter edges (atomic-free).
// Re-zeroes g_hist (zero-on-entry invariant).
__global__ void k_scan_scatter(const int* __restrict__ src,
                               const int* __restrict__ dst,
                               int n_nodes, int n_edges) {
    __shared__ int wsum[32];
    __shared__ int s_off;
    int i    = blockIdx.x * SCAN_B + threadIdx.x;
    int lane = threadIdx.x & 31;
    int wid  = threadIdx.x >> 5;

    // ----- phase 1: global exclusive scan of hist -> rowptr -----
    int v = (i < n_nodes) ? g_hist[i] : 0;
    if (i < n_nodes) g_hist[i] = 0;                  // restore invariant
    int x = warp_iscan(v, lane);
    if (lane == 31) wsum[wid] = x;
    __syncthreads();
    if (wid == 0) wsum[lane] = warp_iscan(wsum[lane], lane);
    __syncthreads();
    int off_local = wid ? wsum[wid - 1] : 0;
    int block_total = wsum[31];

    if (threadIdx.x == 0) {
        g_bsums[blockIdx.x] = block_total;
        __threadfence();
        atomicExch(&g_ready[blockIdx.x], 1);
    }

    int bv = 0;
    if ((int)threadIdx.x < (int)blockIdx.x) {
        while (atomicAdd(&g_ready[threadIdx.x], 0) == 0) {}
        __threadfence();
        bv = g_bsums[threadIdx.x];
    }
    #pragma unroll
    for (int o = 16; o; o >>= 1) bv += __shfl_xor_sync(0xffffffffu, bv, o);
    __syncthreads();                 // wsum reuse barrier
    if (lane == 0) wsum[wid] = bv;
    __syncthreads();
    if (wid == 0) {
        int r = wsum[lane];
        #pragma unroll
        for (int o = 16; o; o >>= 1) r += __shfl_xor_sync(0xffffffffu, r, o);
        if (lane == 0) s_off = r;
    }
    __syncthreads();

    if (i < n_nodes) g_rowptr[i] = off_local + x - v + s_off;
    if (i == 0) g_rowptr[n_nodes] = n_edges;

    // ----- grid barrier: all rowptr chunks globally visible -----
    __syncthreads();                 // all writes of this block issued
    if (threadIdx.x == 0) {
        __threadfence();
        atomicExch(&g_ready2[blockIdx.x], 1);
    }
    if ((int)threadIdx.x < (int)gridDim.x) {
        while (atomicAdd(&g_ready2[threadIdx.x], 0) == 0) {}
    }
    __syncthreads();
    __threadfence();                 // acquire peers' rowptr writes

    // ----- phase 2: atomic-free scatter (grid-stride) -----
    int stride = gridDim.x * SCAN_B;
    for (int e = blockIdx.x * SCAN_B + threadIdx.x; e < n_edges; e += stride) {
        int d = dst[e];
        int s = src[e];
        int p = g_rowptr[d] + g_rank[e];
        g_esrc[p] = s;
    }
}

// ---------------------------------------------------------------------------
// C: fused softmax + aggregation. Warp per dst, 8 lanes per edge (4 edges
// per warp-iter). R10 codegen (no launch_bounds — measured best).
__global__ void k_agg(const float* __restrict__ feat,
                      const float* __restrict__ beta,
                      float* __restrict__ out, int n_nodes) {
    int w    = (blockIdx.x * blockDim.x + threadIdx.x) >> 5;
    int lane = threadIdx.x & 31;
    if (w >= n_nodes) return;
    int grp = lane >> 3;       // which edge of the quad (0..3)
    int g   = lane & 7;        // lane within group

    const float4* feat4 = reinterpret_cast<const float4*>(feat);
    float4 fda = feat4[(size_t)w * 16 + g];
    float4 fdb = feat4[(size_t)w * 16 + g + 8];
    float bscale = beta[0] * g_invn[w];     // TEMP == 1
    int beg = g_rowptr[w], end = g_rowptr[w + 1];
    int deg = end - beg;
    int nfull = deg >> 2;                   // full quads, no predication
    int rem   = deg & 3;

    float denom = 0.0f;
    float4 A = make_float4(0.f, 0.f, 0.f, 0.f);
    float4 B = make_float4(0.f, 0.f, 0.f, 0.f);

    for (int it = 0; it < nfull; it++) {
        int e = beg + it * 4 + grp;
        int s = g_esrc[e];
        float iv = g_invn[s];
        const float4* rp = feat4 + (size_t)s * 16;
        float4 a = rp[g];
        float4 b = rp[g + 8];
        float p = a.x * fda.x + a.y * fda.y + a.z * fda.z + a.w * fda.w
                + b.x * fdb.x + b.y * fdb.y + b.z * fdb.z + b.w * fdb.w;
        p += __shfl_xor_sync(0xffffffffu, p, 4);
        p += __shfl_xor_sync(0xffffffffu, p, 2);
        p += __shfl_xor_sync(0xffffffffu, p, 1);
        float ex = __expf(bscale * iv * p);
        denom += ex;
        A.x += ex * a.x; A.y += ex * a.y; A.z += ex * a.z; A.w += ex * a.w;
        B.x += ex * b.x; B.y += ex * b.y; B.z += ex * b.z; B.w += ex * b.w;
    }
    if (rem) {                              // tail quad, predicated once
        int e = beg + nfull * 4 + grp;
        bool valid = (grp < rem);
        int s = valid ? g_esrc[e] : 0;
        float iv = g_invn[s];
        const float4* rp = feat4 + (size_t)s * 16;
        float4 a = rp[g];
        float4 b = rp[g + 8];
        float p = a.x * fda.x + a.y * fda.y + a.z * fda.z + a.w * fda.w
                + b.x * fdb.x + b.y * fdb.y + b.z * fdb.z + b.w * fdb.w;
        p += __shfl_xor_sync(0xffffffffu, p, 4);
        p += __shfl_xor_sync(0xffffffffu, p, 2);
        p += __shfl_xor_sync(0xffffffffu, p, 1);
        float ex = valid ? __expf(bscale * iv * p) : 0.0f;
        denom += ex;
        A.x += ex * a.x; A.y += ex * a.y; A.z += ex * a.z; A.w += ex * a.w;
        B.x += ex * b.x; B.y += ex * b.y; B.z += ex * b.z; B.w += ex * b.w;
    }

    // combine the 4 edge-groups (lane g in each group owns the same dims)
    #pragma unroll
    for (int o = 8; o <= 16; o <<= 1) {
        denom += __shfl_xor_sync(0xffffffffu, denom, o);
        A.x += __shfl_xor_sync(0xffffffffu, A.x, o);
        A.y += __shfl_xor_sync(0xffffffffu, A.y, o);
        A.z += __shfl_xor_sync(0xffffffffu, A.z, o);
        A.w += __shfl_xor_sync(0xffffffffu, A.w, o);
        B.x += __shfl_xor_sync(0xffffffffu, B.x, o);
        B.y += __shfl_xor_sync(0xffffffffu, B.y, o);
        B.z += __shfl_xor_sync(0xffffffffu, B.z, o);
        B.w += __shfl_xor_sync(0xffffffffu, B.w, o);
    }

    if (lane < 8) {
        float r = 1.0f / fmaxf(denom, EPSV);
        float4 o1 = make_float4(A.x * r, A.y * r, A.z * r, A.w * r);
        float4 o2 = make_float4(B.x * r, B.y * r, B.z * r, B.w * r);
        float4* out4 = reinterpret_cast<float4*>(out);
        out4[(size_t)w * 16 + g]     = o1;
        out4[(size_t)w * 16 + g + 8] = o2;
    }
}

// ---------------------------------------------------------------------------
extern "C" void kernel_launch(void* const* d_in, const int* in_sizes, int n_in,
                              void* d_out, int out_size) {
    const float* feat = (const float*)d_in[0];
    const float* beta = (const float*)d_in[1];
    const int*   src  = (const int*)d_in[2];   // JAX default int32 (no x64)
    const int*   dst  = (const int*)d_in[3];
    float*       out  = (float*)d_out;

    int n_nodes = in_sizes[0] / D;
    int n_edges = in_sizes[2];
    if (n_nodes > NN_MAX) n_nodes = NN_MAX;
    if (n_edges > EE_MAX) n_edges = EE_MAX;

    const int T = 256;
    int roww_blocks = (n_nodes + 7) / 8;          // warp-per-row/dst
    int scan_blocks = (n_nodes + SCAN_B - 1) / SCAN_B;   // <= 128 required

    k_norm_hist   <<<roww_blocks, T>>>(feat, dst, n_nodes, n_edges);
    k_scan_scatter<<<scan_blocks, SCAN_B>>>(src, dst, n_nodes, n_edges);
    k_agg         <<<roww_blocks, T>>>(feat, beta, out, n_nodes);
}

// round 13
// speedup vs baseline: 1.0720x; 1.0613x over previous
#include <cuda_runtime.h>

#define NN_MAX 100000
#define EE_MAX 1600000
#define D 64
#define EPSV 1e-12f
#define SCAN_B 1024

// Scratch (no allocations allowed)
__device__ float g_invn[NN_MAX];        // 1/max(||feat_row||, eps)
__device__ int   g_hist[NN_MAX];        // in-degree (zero-on-entry invariant)
__device__ int   g_rank[EE_MAX];        // edge rank within its dst bucket
__device__ int   g_rowptr[NN_MAX + 1];  // CSR row pointers (by dst)
__device__ int   g_bsums[128];          // scan block totals
__device__ int   g_ready[128];          // scan publish flags (zeroed by A)
__device__ int   g_esrc[EE_MAX];        // src ids grouped by dst

// ---------------------------------------------------------------------------
// A: per-row inverse L2 norm (warp per row) + hist/rank (edge grid-stride)
//    + zero the scan flags for kernel B.
__global__ void k_norm_hist(const float* __restrict__ feat,
                            const int* __restrict__ dst,
                            int n_nodes, int n_edges) {
    int t    = blockIdx.x * blockDim.x + threadIdx.x;
    int w    = t >> 5;
    int lane = threadIdx.x & 31;

    if (t < 128) g_ready[t] = 0;

    if (w < n_nodes) {
        float2 v = reinterpret_cast<const float2*>(feat + (size_t)w * D)[lane];
        float s = v.x * v.x + v.y * v.y;
        #pragma unroll
        for (int o = 16; o; o >>= 1) s += __shfl_xor_sync(0xffffffffu, s, o);
        if (lane == 0) g_invn[w] = 1.0f / fmaxf(sqrtf(s), EPSV);
    }

    int stride = gridDim.x * blockDim.x;
    for (int i = t; i < n_edges; i += stride)
        g_rank[i] = atomicAdd(&g_hist[dst[i]], 1);   // rank within bucket
}

// warp-shuffle inclusive scan helper
__device__ __forceinline__ int warp_iscan(int x, int lane) {
    #pragma unroll
    for (int o = 1; o < 32; o <<= 1) {
        int t = __shfl_up_sync(0xffffffffu, x, o);
        if (lane >= o) x += t;
    }
    return x;
}

// B: single-launch scan (<=128 resident blocks, flag-poll barrier).
// Re-zeroes g_hist (zero-on-entry invariant).
__global__ void k_scan(int n_nodes, int n_edges) {
    __shared__ int wsum[32];
    __shared__ int s_off;
    int i    = blockIdx.x * SCAN_B + threadIdx.x;
    int lane = threadIdx.x & 31;
    int wid  = threadIdx.x >> 5;

    int v = (i < n_nodes) ? g_hist[i] : 0;
    if (i < n_nodes) g_hist[i] = 0;                  // restore invariant
    int x = warp_iscan(v, lane);
    if (lane == 31) wsum[wid] = x;
    __syncthreads();
    if (wid == 0) wsum[lane] = warp_iscan(wsum[lane], lane);
    __syncthreads();
    int off_local = wid ? wsum[wid - 1] : 0;
    int block_total = wsum[31];

    if (threadIdx.x == 0) {
        g_bsums[blockIdx.x] = block_total;
        __threadfence();
        atomicExch(&g_ready[blockIdx.x], 1);
    }

    int bv = 0;
    if ((int)threadIdx.x < (int)blockIdx.x) {
        while (atomicAdd(&g_ready[threadIdx.x], 0) == 0) {}
        __threadfence();
        bv = g_bsums[threadIdx.x];
    }
    #pragma unroll
    for (int o = 16; o; o >>= 1) bv += __shfl_xor_sync(0xffffffffu, bv, o);
    __syncthreads();                 // wsum reuse barrier
    if (lane == 0) wsum[wid] = bv;
    __syncthreads();
    if (wid == 0) {
        int r = wsum[lane];
        #pragma unroll
        for (int o = 16; o; o >>= 1) r += __shfl_xor_sync(0xffffffffu, r, o);
        if (lane == 0) s_off = r;
    }
    __syncthreads();

    if (i < n_nodes) g_rowptr[i] = off_local + x - v + s_off;
    if (i == 0) g_rowptr[n_nodes] = n_edges;
}

// C: atomic-free scatter: pos = rowptr[dst] + rank (4 edges/thread)
__global__ void k_scatter(const int* __restrict__ src,
                          const int* __restrict__ dst, int n_edges) {
    int base = blockIdx.x * (blockDim.x * 4) + threadIdx.x;
    int d[4], s[4], r[4];
    bool v[4];
    #pragma unroll
    for (int k = 0; k < 4; k++) {
        int i = base + k * blockDim.x;
        v[k] = (i < n_edges);
        d[k] = v[k] ? dst[i] : 0;
        s[k] = v[k] ? src[i] : 0;
        r[k] = v[k] ? g_rank[i] : 0;
    }
    int p[4];
    #pragma unroll
    for (int k = 0; k < 4; k++)
        p[k] = g_rowptr[d[k]] + r[k];
    #pragma unroll
    for (int k = 0; k < 4; k++)
        if (v[k]) g_esrc[p[k]] = s[k];
}

// ---------------------------------------------------------------------------
// D: fused softmax + aggregation. Warp per dst, 8 lanes per edge (4 edges per
// warp-iter). SOFTWARE-PIPELINED: iteration i+1's esrc/invn/row loads issue
// before iteration i's shfl/exp/FMA tail, hiding the ~240-cyc L2 gather.
__global__ void k_agg(const float* __restrict__ feat,
                      const float* __restrict__ beta,
                      float* __restrict__ out, int n_nodes) {
    int w    = (blockIdx.x * blockDim.x + threadIdx.x) >> 5;
    int lane = threadIdx.x & 31;
    if (w >= n_nodes) return;
    int grp = lane >> 3;       // which edge of the quad (0..3)
    int g   = lane & 7;        // lane within group

    const float4* feat4 = reinterpret_cast<const float4*>(feat);
    float4 fda = feat4[(size_t)w * 16 + g];
    float4 fdb = feat4[(size_t)w * 16 + g + 8];
    float bscale = beta[0] * g_invn[w];     // TEMP == 1
    int beg = g_rowptr[w], end = g_rowptr[w + 1];
    int deg = end - beg;
    int nfull = deg >> 2;                   // full quads, no predication
    int rem   = deg & 3;

    float denom = 0.0f;
    float4 A = make_float4(0.f, 0.f, 0.f, 0.f);
    float4 B = make_float4(0.f, 0.f, 0.f, 0.f);

    // pipeline prologue: load quad 0
    float4 a_n, b_n;
    float  iv_n = 0.0f;
    if (nfull > 0) {
        int s0 = g_esrc[beg + grp];
        iv_n = g_invn[s0];
        const float4* rp = feat4 + (size_t)s0 * 16;
        a_n = rp[g];
        b_n = rp[g + 8];
    }

    for (int it = 0; it < nfull; it++) {
        float4 a = a_n, b = b_n;
        float  iv = iv_n;
        if (it + 1 < nfull) {               // prefetch quad it+1
            int s1 = g_esrc[beg + (it + 1) * 4 + grp];
            iv_n = g_invn[s1];
            const float4* rp = feat4 + (size_t)s1 * 16;
            a_n = rp[g];
            b_n = rp[g + 8];
        }
        float p = a.x * fda.x + a.y * fda.y + a.z * fda.z + a.w * fda.w
                + b.x * fdb.x + b.y * fdb.y + b.z * fdb.z + b.w * fdb.w;
        p += __shfl_xor_sync(0xffffffffu, p, 4);
        p += __shfl_xor_sync(0xffffffffu, p, 2);
        p += __shfl_xor_sync(0xffffffffu, p, 1);
        float ex = __expf(bscale * iv * p);
        denom += ex;
        A.x += ex * a.x; A.y += ex * a.y; A.z += ex * a.z; A.w += ex * a.w;
        B.x += ex * b.x; B.y += ex * b.y; B.z += ex * b.z; B.w += ex * b.w;
    }
    if (rem) {                              // tail quad, predicated once
        int e = beg + nfull * 4 + grp;
        bool valid = (grp < rem);
        int s = valid ? g_esrc[e] : 0;
        float iv = g_invn[s];
        const float4* rp = feat4 + (size_t)s * 16;
        float4 a = rp[g];
        float4 b = rp[g + 8];
        float p = a.x * fda.x + a.y * fda.y + a.z * fda.z + a.w * fda.w
                + b.x * fdb.x + b.y * fdb.y + b.z * fdb.z + b.w * fdb.w;
        p += __shfl_xor_sync(0xffffffffu, p, 4);
        p += __shfl_xor_sync(0xffffffffu, p, 2);
        p += __shfl_xor_sync(0xffffffffu, p, 1);
        float ex = valid ? __expf(bscale * iv * p) : 0.0f;
        denom += ex;
        A.x += ex * a.x; A.y += ex * a.y; A.z += ex * a.z; A.w += ex * a.w;
        B.x += ex * b.x; B.y += ex * b.y; B.z += ex * b.z; B.w += ex * b.w;
    }

    // combine the 4 edge-groups (lane g in each group owns the same dims)
    #pragma unroll
    for (int o = 8; o <= 16; o <<= 1) {
        denom += __shfl_xor_sync(0xffffffffu, denom, o);
        A.x += __shfl_xor_sync(0xffffffffu, A.x, o);
        A.y += __shfl_xor_sync(0xffffffffu, A.y, o);
        A.z += __shfl_xor_sync(0xffffffffu, A.z, o);
        A.w += __shfl_xor_sync(0xffffffffu, A.w, o);
        B.x += __shfl_xor_sync(0xffffffffu, B.x, o);
        B.y += __shfl_xor_sync(0xffffffffu, B.y, o);
        B.z += __shfl_xor_sync(0xffffffffu, B.z, o);
        B.w += __shfl_xor_sync(0xffffffffu, B.w, o);
    }

    if (lane < 8) {
        float r = 1.0f / fmaxf(denom, EPSV);
        float4 o1 = make_float4(A.x * r, A.y * r, A.z * r, A.w * r);
        float4 o2 = make_float4(B.x * r, B.y * r, B.z * r, B.w * r);
        float4* out4 = reinterpret_cast<float4*>(out);
        out4[(size_t)w * 16 + g]     = o1;
        out4[(size_t)w * 16 + g + 8] = o2;
    }
}

// ---------------------------------------------------------------------------
extern "C" void kernel_launch(void* const* d_in, const int* in_sizes, int n_in,
                              void* d_out, int out_size) {
    const float* feat = (const float*)d_in[0];
    const float* beta = (const float*)d_in[1];
    const int*   src  = (const int*)d_in[2];   // JAX default int32 (no x64)
    const int*   dst  = (const int*)d_in[3];
    float*       out  = (float*)d_out;

    int n_nodes = in_sizes[0] / D;
    int n_edges = in_sizes[2];
    if (n_nodes > NN_MAX) n_nodes = NN_MAX;
    if (n_edges > EE_MAX) n_edges = EE_MAX;

    const int T = 256;
    int roww_blocks = (n_nodes + 7) / 8;          // warp-per-row/dst
    int scat_blocks = (n_edges + T * 4 - 1) / (T * 4);
    int scan_blocks = (n_nodes + SCAN_B - 1) / SCAN_B;   // <= 128 required

    k_norm_hist<<<roww_blocks, T>>>(feat, dst, n_nodes, n_edges);
    k_scan     <<<scan_blocks, SCAN_B>>>(n_nodes, n_edges);
    k_scatter  <<<scat_blocks, T>>>(src, dst, n_edges);
    k_agg      <<<roww_blocks, T>>>(feat, beta, out, n_nodes);
}

// round 14
// speedup vs baseline: 1.0765x; 1.0041x over previous
#include <cuda_runtime.h>

#define NN_MAX 100000
#define EE_MAX 1600000
#define D 64
#define EPSV 1e-12f
#define SCAN_B 1024

// Scratch (no allocations allowed)
__device__ float g_invn[NN_MAX];        // 1/max(||feat_row||, eps)
__device__ int   g_hist[NN_MAX];        // in-degree (zero-on-entry invariant)
__device__ int   g_rank[EE_MAX];        // edge rank within its dst bucket
__device__ int   g_rowptr[NN_MAX + 1];  // CSR row pointers (by dst)
__device__ int   g_bsums[128];          // scan block totals
__device__ int   g_ready[128];          // scan publish flags (zeroed by A)
__device__ int   g_esrc[EE_MAX];        // src ids grouped by dst

// ---------------------------------------------------------------------------
// A: per-row inverse L2 norm (warp per row) + hist/rank (edge grid-stride)
//    + zero the scan flags for kernel B.
__global__ void k_norm_hist(const float* __restrict__ feat,
                            const int* __restrict__ dst,
                            int n_nodes, int n_edges) {
    int t    = blockIdx.x * blockDim.x + threadIdx.x;
    int w    = t >> 5;
    int lane = threadIdx.x & 31;

    if (t < 128) g_ready[t] = 0;

    if (w < n_nodes) {
        float2 v = reinterpret_cast<const float2*>(feat + (size_t)w * D)[lane];
        float s = v.x * v.x + v.y * v.y;
        #pragma unroll
        for (int o = 16; o; o >>= 1) s += __shfl_xor_sync(0xffffffffu, s, o);
        if (lane == 0) g_invn[w] = 1.0f / fmaxf(sqrtf(s), EPSV);
    }

    int stride = gridDim.x * blockDim.x;
    for (int i = t; i < n_edges; i += stride)
        g_rank[i] = atomicAdd(&g_hist[dst[i]], 1);   // rank within bucket
}

// warp-shuffle inclusive scan helper
__device__ __forceinline__ int warp_iscan(int x, int lane) {
    #pragma unroll
    for (int o = 1; o < 32; o <<= 1) {
        int t = __shfl_up_sync(0xffffffffu, x, o);
        if (lane >= o) x += t;
    }
    return x;
}

// B: single-launch scan (<=128 resident blocks, flag-poll barrier).
// Re-zeroes g_hist (zero-on-entry invariant).
__global__ void k_scan(int n_nodes, int n_edges) {
    __shared__ int wsum[32];
    __shared__ int s_off;
    int i    = blockIdx.x * SCAN_B + threadIdx.x;
    int lane = threadIdx.x & 31;
    int wid  = threadIdx.x >> 5;

    int v = (i < n_nodes) ? g_hist[i] : 0;
    if (i < n_nodes) g_hist[i] = 0;                  // restore invariant
    int x = warp_iscan(v, lane);
    if (lane == 31) wsum[wid] = x;
    __syncthreads();
    if (wid == 0) wsum[lane] = warp_iscan(wsum[lane], lane);
    __syncthreads();
    int off_local = wid ? wsum[wid - 1] : 0;
    int block_total = wsum[31];

    if (threadIdx.x == 0) {
        g_bsums[blockIdx.x] = block_total;
        __threadfence();
        atomicExch(&g_ready[blockIdx.x], 1);
    }

    int bv = 0;
    if ((int)threadIdx.x < (int)blockIdx.x) {
        while (atomicAdd(&g_ready[threadIdx.x], 0) == 0) {}
        __threadfence();
        bv = g_bsums[threadIdx.x];
    }
    #pragma unroll
    for (int o = 16; o; o >>= 1) bv += __shfl_xor_sync(0xffffffffu, bv, o);
    __syncthreads();                 // wsum reuse barrier
    if (lane == 0) wsum[wid] = bv;
    __syncthreads();
    if (wid == 0) {
        int r = wsum[lane];
        #pragma unroll
        for (int o = 16; o; o >>= 1) r += __shfl_xor_sync(0xffffffffu, r, o);
        if (lane == 0) s_off = r;
    }
    __syncthreads();

    if (i < n_nodes) g_rowptr[i] = off_local + x - v + s_off;
    if (i == 0) g_rowptr[n_nodes] = n_edges;
}

// C: atomic-free scatter: pos = rowptr[dst] + rank (4 edges/thread)
__global__ void k_scatter(const int* __restrict__ src,
                          const int* __restrict__ dst, int n_edges) {
    int base = blockIdx.x * (blockDim.x * 4) + threadIdx.x;
    int d[4], s[4], r[4];
    bool v[4];
    #pragma unroll
    for (int k = 0; k < 4; k++) {
        int i = base + k * blockDim.x;
        v[k] = (i < n_edges);
        d[k] = v[k] ? dst[i] : 0;
        s[k] = v[k] ? src[i] : 0;
        r[k] = v[k] ? g_rank[i] : 0;
    }
    int p[4];
    #pragma unroll
    for (int k = 0; k < 4; k++)
        p[k] = g_rowptr[d[k]] + r[k];
    #pragma unroll
    for (int k = 0; k < 4; k++)
        if (v[k]) g_esrc[p[k]] = s[k];
}

// ---------------------------------------------------------------------------
// D: fused softmax + aggregation. Warp per dst, 8 lanes per edge (4 edges per
// warp-iter). TWO-DEPTH software pipeline: edge INDEX prefetched at depth 2,
// row DATA at depth 1 — breaks the serial esrc->row 480-cyc chain so only
// one ~240-cyc L2 latency is exposed per iteration.
__global__ void k_agg(const float* __restrict__ feat,
                      const float* __restrict__ beta,
                      float* __restrict__ out, int n_nodes) {
    int w    = (blockIdx.x * blockDim.x + threadIdx.x) >> 5;
    int lane = threadIdx.x & 31;
    if (w >= n_nodes) return;
    int grp = lane >> 3;       // which edge of the quad (0..3)
    int g   = lane & 7;        // lane within group

    const float4* feat4 = reinterpret_cast<const float4*>(feat);
    float4 fda = feat4[(size_t)w * 16 + g];
    float4 fdb = feat4[(size_t)w * 16 + g + 8];
    float bscale = beta[0] * g_invn[w];     // TEMP == 1
    int beg = g_rowptr[w], end = g_rowptr[w + 1];
    int deg = end - beg;
    int nfull = deg >> 2;                   // full quads, no predication
    int rem   = deg & 3;

    float denom = 0.0f;
    float4 A = make_float4(0.f, 0.f, 0.f, 0.f);
    float4 B = make_float4(0.f, 0.f, 0.f, 0.f);

    // prologue: index for quad 0 and quad 1; row data for quad 0
    int s_cur = (nfull > 0) ? g_esrc[beg + grp] : 0;
    int s_nx  = (nfull > 1) ? g_esrc[beg + 4 + grp] : 0;
    float4 a_n, b_n;
    float  iv_n = 0.0f;
    if (nfull > 0) {
        iv_n = g_invn[s_cur];
        const float4* rp = feat4 + (size_t)s_cur * 16;
        a_n = rp[g];
        b_n = rp[g + 8];
    }

    for (int it = 0; it < nfull; it++) {
        float4 a = a_n, b = b_n;
        float  iv = iv_n;
        s_cur = s_nx;                           // index for it+1 (arrived)
        if (it + 2 < nfull)                     // index prefetch, depth 2
            s_nx = g_esrc[beg + (it + 2) * 4 + grp];
        if (it + 1 < nfull) {                   // row prefetch, depth 1
            iv_n = g_invn[s_cur];
            const float4* rp = feat4 + (size_t)s_cur * 16;
            a_n = rp[g];
            b_n = rp[g + 8];
        }
        float p = a.x * fda.x + a.y * fda.y + a.z * fda.z + a.w * fda.w
                + b.x * fdb.x + b.y * fdb.y + b.z * fdb.z + b.w * fdb.w;
        p += __shfl_xor_sync(0xffffffffu, p, 4);
        p += __shfl_xor_sync(0xffffffffu, p, 2);
        p += __shfl_xor_sync(0xffffffffu, p, 1);
        float ex = __expf(bscale * iv * p);
        denom += ex;
        A.x += ex * a.x; A.y += ex * a.y; A.z += ex * a.z; A.w += ex * a.w;
        B.x += ex * b.x; B.y += ex * b.y; B.z += ex * b.z; B.w += ex * b.w;
    }
    if (rem) {                              // tail quad, predicated once
        int e = beg + nfull * 4 + grp;
        bool valid = (grp < rem);
        int s = valid ? g_esrc[e] : 0;
        float iv = g_invn[s];
        const float4* rp = feat4 + (size_t)s * 16;
        float4 a = rp[g];
        float4 b = rp[g + 8];
        float p = a.x * fda.x + a.y * fda.y + a.z * fda.z + a.w * fda.w
                + b.x * fdb.x + b.y * fdb.y + b.z * fdb.z + b.w * fdb.w;
        p += __shfl_xor_sync(0xffffffffu, p, 4);
        p += __shfl_xor_sync(0xffffffffu, p, 2);
        p += __shfl_xor_sync(0xffffffffu, p, 1);
        float ex = valid ? __expf(bscale * iv * p) : 0.0f;
        denom += ex;
        A.x += ex * a.x; A.y += ex * a.y; A.z += ex * a.z; A.w += ex * a.w;
        B.x += ex * b.x; B.y += ex * b.y; B.z += ex * b.z; B.w += ex * b.w;
    }

    // combine the 4 edge-groups (lane g in each group owns the same dims)
    #pragma unroll
    for (int o = 8; o <= 16; o <<= 1) {
        denom += __shfl_xor_sync(0xffffffffu, denom, o);
        A.x += __shfl_xor_sync(0xffffffffu, A.x, o);
        A.y += __shfl_xor_sync(0xffffffffu, A.y, o);
        A.z += __shfl_xor_sync(0xffffffffu, A.z, o);
        A.w += __shfl_xor_sync(0xffffffffu, A.w, o);
        B.x += __shfl_xor_sync(0xffffffffu, B.x, o);
        B.y += __shfl_xor_sync(0xffffffffu, B.y, o);
        B.z += __shfl_xor_sync(0xffffffffu, B.z, o);
        B.w += __shfl_xor_sync(0xffffffffu, B.w, o);
    }

    if (lane < 8) {
        float r = 1.0f / fmaxf(denom, EPSV);
        float4 o1 = make_float4(A.x * r, A.y * r, A.z * r, A.w * r);
        float4 o2 = make_float4(B.x * r, B.y * r, B.z * r, B.w * r);
        float4* out4 = reinterpret_cast<float4*>(out);
        out4[(size_t)w * 16 + g]     = o1;
        out4[(size_t)w * 16 + g + 8] = o2;
    }
}

// ---------------------------------------------------------------------------
extern "C" void kernel_launch(void* const* d_in, const int* in_sizes, int n_in,
                              void* d_out, int out_size) {
    const float* feat = (const float*)d_in[0];
    const float* beta = (const float*)d_in[1];
    const int*   src  = (const int*)d_in[2];   // JAX default int32 (no x64)
    const int*   dst  = (const int*)d_in[3];
    float*       out  = (float*)d_out;

    int n_nodes = in_sizes[0] / D;
    int n_edges = in_sizes[2];
    if (n_nodes > NN_MAX) n_nodes = NN_MAX;
    if (n_edges > EE_MAX) n_edges = EE_MAX;

    const int T = 256;
    int roww_blocks = (n_nodes + 7) / 8;          // warp-per-row/dst
    int scat_blocks = (n_edges + T * 4 - 1) / (T * 4);
    int scan_blocks = (n_nodes + SCAN_B - 1) / SCAN_B;   // <= 128 required

    k_norm_hist<<<roww_blocks, T>>>(feat, dst, n_nodes, n_edges);
    k_scan     <<<scan_blocks, SCAN_B>>>(n_nodes, n_edges);
    k_scatter  <<<scat_blocks, T>>>(src, dst, n_edges);
    k_agg      <<<roww_blocks, T>>>(feat, beta, out, n_nodes);
}